// round 15
// baseline (speedup 1.0000x reference)
#include <cuda_runtime.h>
#include <cuda_bf16.h>
#include <stdint.h>

typedef unsigned long long u64;

#define QNUM 10000
#define DNUM 64
#define MNUM 50
#define BNUM 64
#define TNUM 512
#define PART_STRIDE ((size_t)BNUM * (TNUM - 1) * DNUM)   // floats per partial stream

#define RB 48        // rows per build block
#define SVSTR 68     // padded staging stride (floats); 272B = 16B-aligned rows
#define WKFB 209     // ceil(10000/48)
#define EAB 417      // ceil(20000/48)

// ---------------- static scratch (no allocations allowed) ----------------
__device__ __align__(16) float g_kf [QNUM * DNUM];          // k-half of f-MLP + bias, per question id
__device__ __align__(16) float g_e  [2 * QNUM * DNUM];      // sigmoid erase per x id (raw)
__device__ __align__(16) float g_a  [2 * QNUM * DNUM];      // tanh add per x id (raw)
__device__ __align__(16) float g_wp [QNUM * 128];           // packed (w,w) pairs: pair j = w[m=j], j<50
__device__ __align__(16) float g_part[2 * PART_STRIDE];     // 2 partial read streams (split halves)

// ---------------- f32x2 helpers ----------------
__device__ __forceinline__ u64 f2pk(float a, float b) {
    u64 r; asm("mov.b64 %0,{%1,%2};" : "=l"(r) : "f"(a), "f"(b)); return r;
}
__device__ __forceinline__ u64 f2bc(float a) {
    u64 r; asm("mov.b64 %0,{%1,%1};" : "=l"(r) : "f"(a)); return r;
}
__device__ __forceinline__ void f2up(u64 v, float& a, float& b) {
    asm("mov.b64 {%0,%1},%2;" : "=f"(a), "=f"(b) : "l"(v));
}
__device__ __forceinline__ u64 f2fma(u64 a, u64 b, u64 c) {
    u64 d; asm("fma.rn.f32x2 %0,%1,%2,%3;" : "=l"(d) : "l"(a), "l"(b), "l"(c)); return d;
}
__device__ __forceinline__ u64 f2mul(u64 a, u64 b) {
    u64 d; asm("mul.rn.f32x2 %0,%1,%2;" : "=l"(d) : "l"(a), "l"(b)); return d;
}
__device__ __forceinline__ u64 f2add(u64 a, u64 b) {
    u64 d; asm("add.rn.f32x2 %0,%1,%2;" : "=l"(d) : "l"(a), "l"(b)); return d;
}

__device__ __forceinline__ float sigfast(float x) {
    return __fdividef(1.f, 1.f + __expf(-x));
}
__device__ __forceinline__ float tanhfast(float x) {
    x = fminf(fmaxf(x, -10.f), 10.f);
    float t = __expf(2.f * x);
    return (t - 1.f) * __fdividef(1.f, t + 1.f);
}

// ---------------- cp.async helpers ----------------
__device__ __forceinline__ void cpa16(uint32_t dst, const void* src) {
    asm volatile("cp.async.ca.shared.global [%0], [%1], 16;\n" :: "r"(dst), "l"(src));
}
__device__ __forceinline__ void cpcommit() { asm volatile("cp.async.commit_group;\n"); }
template <int N> __device__ __forceinline__ void cpwait() {
    asm volatile("cp.async.wait_group %0;\n" :: "n"(N));
}

// =====================================================================
// K1: precompute, fused dual-GEMM per block, 48 rows/CTA, 128 threads.
// (Exact round-10 version — best measured: 23.1us.)
// =====================================================================
__global__ void __launch_bounds__(128) k_build(
    const float* __restrict__ k_emb, const float* __restrict__ Mk,
    const float* __restrict__ fW, const float* __restrict__ fb,
    const float* __restrict__ v_emb,
    const float* __restrict__ eW, const float* __restrict__ eb,
    const float* __restrict__ aW, const float* __restrict__ ab)
{
    __shared__ __align__(16) float sV[RB * SVSTR];   // 12.8KB staged input rows
    __shared__ __align__(16) u64 sW1[64 * 32];       // 16KB matrix 1 (pairs)
    __shared__ __align__(16) u64 sW2[64 * 32];       // 16KB matrix 2 (pairs)

    int tid = threadIdx.x;
    int warp = tid >> 5, lane = tid & 31;
    int tr = lane >> 3, tc = lane & 7;
    int lr0 = warp * 12 + tr;              // local rows lr0 + 4*j, j<3

    bool iswkf = blockIdx.x < WKFB;
    int rbase = iswkf ? blockIdx.x * RB : (blockIdx.x - WKFB) * RB;
    int nmax  = iswkf ? QNUM : 2 * QNUM;
    const float* src = iswkf ? k_emb : v_emb;

    uint32_t svd  = (uint32_t)__cvta_generic_to_shared(sV);
    uint32_t sw1d = (uint32_t)__cvta_generic_to_shared(sW1);
    uint32_t sw2d = (uint32_t)__cvta_generic_to_shared(sW2);

    // stage input rows (48 x 64 floats)
    for (int idx = tid; idx < RB * 16; idx += 128) {
        int r = idx >> 4, c = idx & 15;
        int row = min(rbase + r, nmax - 1);
        cpa16(svd + (r * SVSTR + c * 4) * 4, src + (size_t)row * 64 + c * 4);
    }
    // stage weight matrices
    if (iswkf) {
        for (int idx = tid; idx < 1024; idx += 128)
            cpa16(sw2d + idx * 16, fW + 4096 + idx * 4);     // fW rows 64..127
        // MkT pairs: sW1[i*32+j] = (Mk[2j][i], Mk[2j+1][i]), zero-padded m>=50
        for (int idx = tid; idx < 2048; idx += 128) {
            int j = idx & 31, i = idx >> 5;
            float a = (2 * j < MNUM) ? Mk[(2 * j) * 64 + i] : 0.f;
            float b = (2 * j + 1 < MNUM) ? Mk[(2 * j + 1) * 64 + i] : 0.f;
            sW1[i * 32 + j] = f2pk(a, b);
        }
    } else {
        for (int idx = tid; idx < 1024; idx += 128) {
            cpa16(sw1d + idx * 16, eW + idx * 4);
            cpa16(sw2d + idx * 16, aW + idx * 4);
        }
    }
    cpcommit();

    // init accumulators (strided pair j0 = 8p + tc); scalar bias loads
    u64 acc1[3][4], acc2[3][4];
    {
        const float* b2f = iswkf ? fb : ab;
#pragma unroll
        for (int p = 0; p < 4; p++) {
            int j0 = 8 * p + tc;
            u64 v1 = iswkf ? 0ull : f2pk(eb[2 * j0], eb[2 * j0 + 1]);
            u64 v2 = f2pk(b2f[2 * j0], b2f[2 * j0 + 1]);
#pragma unroll
            for (int j = 0; j < 3; j++) { acc1[j][p] = v1; acc2[j][p] = v2; }
        }
    }

    cpwait<0>();
    __syncthreads();

    // fused dual-GEMM mainloop
#pragma unroll 8
    for (int i = 0; i < 64; i++) {
        u64 w1[4], w2[4];
#pragma unroll
        for (int p = 0; p < 4; p++) {
            w1[p] = sW1[i * 32 + 8 * p + tc];
            w2[p] = sW2[i * 32 + 8 * p + tc];
        }
#pragma unroll
        for (int j = 0; j < 3; j++) {
            u64 rb = f2bc(sV[(lr0 + 4 * j) * SVSTR + i]);
            acc1[j][0] = f2fma(rb, w1[0], acc1[j][0]);
            acc2[j][0] = f2fma(rb, w2[0], acc2[j][0]);
            acc1[j][1] = f2fma(rb, w1[1], acc1[j][1]);
            acc2[j][1] = f2fma(rb, w2[1], acc2[j][1]);
            acc1[j][2] = f2fma(rb, w1[2], acc1[j][2]);
            acc2[j][2] = f2fma(rb, w2[2], acc2[j][2]);
            acc1[j][3] = f2fma(rb, w1[3], acc1[j][3]);
            acc2[j][3] = f2fma(rb, w2[3], acc2[j][3]);
        }
    }

    if (iswkf) {
        // softmax over m (thread owns m-pairs j0 = 8p+tc; pairs >=25 invalid)
#pragma unroll
        for (int j = 0; j < 3; j++) {
            int q = min(rbase + lr0 + 4 * j, QNUM - 1);
            float l[8];
#pragma unroll
            for (int p = 0; p < 4; p++) {
                f2up(acc1[j][p], l[2 * p], l[2 * p + 1]);
                if (8 * p + tc >= 25) { l[2 * p] = -3.0e38f; l[2 * p + 1] = -3.0e38f; }
            }
            float mx = l[0];
#pragma unroll
            for (int k = 1; k < 8; k++) mx = fmaxf(mx, l[k]);
            mx = fmaxf(mx, __shfl_xor_sync(0xffffffffu, mx, 1));
            mx = fmaxf(mx, __shfl_xor_sync(0xffffffffu, mx, 2));
            mx = fmaxf(mx, __shfl_xor_sync(0xffffffffu, mx, 4));
            float sm = 0.f;
#pragma unroll
            for (int k = 0; k < 8; k++) { l[k] = __expf(l[k] - mx); sm += l[k]; }
            sm += __shfl_xor_sync(0xffffffffu, sm, 1);
            sm += __shfl_xor_sync(0xffffffffu, sm, 2);
            sm += __shfl_xor_sync(0xffffffffu, sm, 4);
            float inv = __fdividef(1.f, sm);
            float* wp = g_wp + (size_t)q * 128;
            u64* kfd = (u64*)(g_kf + (size_t)q * 64);
#pragma unroll
            for (int p = 0; p < 4; p++) {
                int j0 = 8 * p + tc;
                float va = l[2 * p] * inv, vb = l[2 * p + 1] * inv;
                *(float4*)(wp + 4 * j0) = make_float4(va, va, vb, vb);
                kfd[j0] = acc2[j][p];
            }
        }
    } else {
        // e = sigmoid(acc1), a = tanh(acc2)
#pragma unroll
        for (int j = 0; j < 3; j++) {
            int x = min(rbase + lr0 + 4 * j, 2 * QNUM - 1);
            u64* ed = (u64*)(g_e + (size_t)x * 64);
            u64* ad = (u64*)(g_a + (size_t)x * 64);
#pragma unroll
            for (int p = 0; p < 4; p++) {
                int j0 = 8 * p + tc;
                float x0, x1;
                f2up(acc1[j][p], x0, x1);
                ed[j0] = f2pk(sigfast(x0), sigfast(x1));
                f2up(acc2[j][p], x0, x1);
                ad[j0] = f2pk(tanhfast(x0), tanhfast(x1));
            }
        }
    }
}

// =====================================================================
// K2: sequential scan with direct gather. 128 CTAs = (64 b) x (2 splits
// of 4 m-groups of 8), 4 warps/CTA. 16 steps/pipeline block, depth-3.
// R10 structure + software-pipelined operand loads: step s+1's w/e/a
// are prefetched into registers while step s computes, hiding the
// 29-cycle LDS latency that capped issue at ~35%.
// =====================================================================
__global__ void __launch_bounds__(128) k_scan(
    const float* __restrict__ Mv0,
    const int* __restrict__ question, const int* __restrict__ response,
    const float* __restrict__ mask)
{
    __shared__ __align__(16) char sme[3][4096];     // raw e rows   12KB
    __shared__ __align__(16) char sma[3][4096];     // raw a rows   12KB
    __shared__ __align__(16) char smw[3][4096];     // packed w     12KB
    __shared__ __align__(16) u64 stag[4][16][32];   // group partials 16KB
    __shared__ int   sxoff[512];                    // x-id * 256 (byte off)
    __shared__ int   sqoff[512];                    // q*512 + split*256
    __shared__ float smask[512];

    int b     = blockIdx.x & 63;
    int split = blockIdx.x >> 6;
    int tid = threadIdx.x;
    int g = tid >> 5, lane = tid & 31;     // local group 0..3
    int gg = split * 4 + g;                // global group 0..7
    int m0 = gg * 8;

    // ---- meta preload ----
    {
        int4 qa = ((const int4*)(question + b * 512))[tid];
        int4 ra = ((const int4*)(response + b * 512))[tid];
        float4 ma = ((const float4*)(mask + b * 512))[tid];
        int base = tid * 4;
        int so = split * 256;
        sxoff[base + 0] = (qa.x + QNUM * ra.x) * 256;  sqoff[base + 0] = qa.x * 512 + so;
        sxoff[base + 1] = (qa.y + QNUM * ra.y) * 256;  sqoff[base + 1] = qa.y * 512 + so;
        sxoff[base + 2] = (qa.z + QNUM * ra.z) * 256;  sqoff[base + 2] = qa.z * 512 + so;
        sxoff[base + 3] = (qa.w + QNUM * ra.w) * 256;  sqoff[base + 3] = qa.w * 512 + so;
        smask[base + 0] = ma.x; smask[base + 1] = ma.y;
        smask[base + 2] = ma.z; smask[base + 3] = ma.w;
    }

    u64 mv[8];
#pragma unroll
    for (int p = 0; p < 8; p++)
        mv[p] = (m0 + p < MNUM) ? *(const u64*)&Mv0[(m0 + p) * 64 + 2 * lane] : 0ull;

    __syncthreads();

    uint32_t sme_d = (uint32_t)__cvta_generic_to_shared(&sme[0][0]);
    uint32_t sma_d = (uint32_t)__cvta_generic_to_shared(&sma[0][0]);
    uint32_t smw_d = (uint32_t)__cvta_generic_to_shared(&smw[0][0]);
    const char* eB = (const char*)g_e;
    const char* aB = (const char*)g_a;
    const char* wB = (const char*)g_wp;

    auto issue = [&](int kb) {
        int buf = kb - (kb / 3) * 3;
        int t0 = kb * 16;
#pragma unroll
        for (int h = 0; h < 2; h++) {
            int c = tid + h * 128;            // 0..255 = 16 steps x 16 chunks
            int s = c >> 4, k16 = (c & 15) * 16;
            int xo = sxoff[t0 + s];
            int qo = sqoff[t0 + s];
            cpa16(sme_d + buf * 4096 + c * 16, eB + xo + k16);
            cpa16(sma_d + buf * 4096 + c * 16, aB + xo + k16);
            cpa16(smw_d + buf * 4096 + c * 16, wB + qo + k16);
        }
    };

    issue(0); cpcommit();
    issue(1); cpcommit();
    issue(2); cpcommit();

    float* pbase = g_part + split * PART_STRIDE + (size_t)b * 511 * 64 + 2 * lane;

    for (int kb = 0; kb < 32; kb++) {
        cpwait<2>();
        __syncthreads();
        int buf = kb - (kb / 3) * 3;
        const u64* eP = (const u64*)sme[buf];
        const u64* aP = (const u64*)sma[buf];
        const u64* wP = (const u64*)smw[buf];

        // preload step-0 operands
        u64 pw[8], pe, pa;
        {
            const u64* wr0 = wP + g * 8;
#pragma unroll
            for (int p = 0; p < 8; p++) pw[p] = wr0[p];
            pe = eP[lane];
            pa = aP[lane];
        }

#pragma unroll
        for (int s = 0; s < 16; s++) {
            // take current operands out of the prefetch registers
            u64 w0 = pw[0], w1 = pw[1], w2 = pw[2], w3 = pw[3],
                w4 = pw[4], w5 = pw[5], w6 = pw[6], w7 = pw[7];
            u64 ev = pe, av = pa;
            // prefetch step s+1 before the FMA chain
            if (s < 15) {
                const u64* wrn = wP + (s + 1) * 32 + g * 8;
#pragma unroll
                for (int p = 0; p < 8; p++) pw[p] = wrn[p];
                pe = eP[(s + 1) * 32 + lane];
                pa = aP[(s + 1) * 32 + lane];
            }
            float mt = smask[kb * 16 + s];
            u64 em2 = f2mul(ev, f2bc(-mt));
            u64 am2 = f2mul(av, f2bc(mt));
            // read (state before this step's update)
            u64 p0 = f2mul(w0, mv[0]);
            u64 p1 = f2mul(w1, mv[1]);
            p0 = f2fma(w2, mv[2], p0);
            p1 = f2fma(w3, mv[3], p1);
            p0 = f2fma(w4, mv[4], p0);
            p1 = f2fma(w5, mv[5], p1);
            p0 = f2fma(w6, mv[6], p0);
            p1 = f2fma(w7, mv[7], p1);
            stag[g][s][lane] = f2add(p0, p1);
            // update: Mv += w * (mt*(a - e*Mv))
            u64 t0;
            t0 = f2fma(em2, mv[0], am2); mv[0] = f2fma(w0, t0, mv[0]);
            t0 = f2fma(em2, mv[1], am2); mv[1] = f2fma(w1, t0, mv[1]);
            t0 = f2fma(em2, mv[2], am2); mv[2] = f2fma(w2, t0, mv[2]);
            t0 = f2fma(em2, mv[3], am2); mv[3] = f2fma(w3, t0, mv[3]);
            t0 = f2fma(em2, mv[4], am2); mv[4] = f2fma(w4, t0, mv[4]);
            t0 = f2fma(em2, mv[5], am2); mv[5] = f2fma(w5, t0, mv[5]);
            t0 = f2fma(em2, mv[6], am2); mv[6] = f2fma(w6, t0, mv[6]);
            t0 = f2fma(em2, mv[7], am2); mv[7] = f2fma(w7, t0, mv[7]);
        }
        __syncthreads();
        // warp g reduces steps 4g..4g+3 across the CTA's 4 groups
#pragma unroll
        for (int ss = 0; ss < 4; ss++) {
            int so = g * 4 + ss;
            int t = kb * 16 + so;
            if (t > 0) {
                u64 a0 = f2add(stag[0][so][lane], stag[1][so][lane]);
                u64 a1 = f2add(stag[2][so][lane], stag[3][so][lane]);
                *(u64*)(pbase + (size_t)(t - 1) * 64) = f2add(a0, a1);
            }
        }
        if (kb + 3 < 32) issue(kb + 3);
        cpcommit();
    }
}

// =====================================================================
// K3: head as register-tiled GEMM. 64 rows/block, grid 511.
// (Exact round-10 version.)
// =====================================================================
#define RSTR 68   // padded read row stride in floats

__global__ void __launch_bounds__(256) k_head(
    const int* __restrict__ question, const float* __restrict__ fW,
    const float* __restrict__ pW, const float* __restrict__ pb,
    float* __restrict__ out)
{
    __shared__ __align__(16) float sW[64 * 64];
    __shared__ __align__(16) float sread[64 * RSTR];
    __shared__ float spw[64];

    int tid = threadIdx.x;
    int warp = tid >> 5, lane = tid & 31;
    int tr = lane >> 3, tc = lane & 7;
    int rbase = blockIdx.x * 64;

    {
        const float4* src = (const float4*)fW;
        float4* dst = (float4*)sW;
        for (int idx = tid; idx < 1024; idx += 256) dst[idx] = src[idx];
        if (tid < 64) spw[tid] = pW[tid];
    }

    {
        const float4* p0 = (const float4*)g_part;
        const float4* p1 = (const float4*)(g_part + PART_STRIDE);
#pragma unroll
        for (int k = 0; k < 4; k++) {
            int idx = k * 256 + tid;
            int r = idx >> 4, c = idx & 15;
            size_t grow = (size_t)(rbase + r) * 16 + c;
            float4 a = p0[grow];
            float4 b4 = p1[grow];
            float4 s;
            s.x = a.x + b4.x; s.y = a.y + b4.y; s.z = a.z + b4.z; s.w = a.w + b4.w;
            *(float4*)&sread[r * RSTR + c * 4] = s;
        }
    }

    int myrow0 = rbase + warp * 8 + tr;        // rows myrow0 + 4*j, j<2
    u64 facc[2][4];
#pragma unroll
    for (int j = 0; j < 2; j++) {
        int row = myrow0 + 4 * j;
        int b = row / 511;
        int tp = row - b * 511;
        int q = question[b * 512 + tp + 1];
        const float4* kfp = (const float4*)&g_kf[(size_t)q * 64 + tc * 8];
        float4 A = kfp[0], B = kfp[1];
        facc[j][0] = f2pk(A.x, A.y);
        facc[j][1] = f2pk(A.z, A.w);
        facc[j][2] = f2pk(B.x, B.y);
        facc[j][3] = f2pk(B.z, B.w);
    }
    __syncthreads();

    const u64* W = (const u64*)sW;
    const float* sr = &sread[(warp * 8 + tr) * RSTR];
#pragma unroll 8
    for (int i = 0; i < 64; i++) {
        u64 w0 = W[i * 32 + tc * 4 + 0];
        u64 w1 = W[i * 32 + tc * 4 + 1];
        u64 w2 = W[i * 32 + tc * 4 + 2];
        u64 w3 = W[i * 32 + tc * 4 + 3];
#pragma unroll
        for (int j = 0; j < 2; j++) {
            u64 rb = f2bc(sr[j * 4 * RSTR + i]);
            facc[j][0] = f2fma(rb, w0, facc[j][0]);
            facc[j][1] = f2fma(rb, w1, facc[j][1]);
            facc[j][2] = f2fma(rb, w2, facc[j][2]);
            facc[j][3] = f2fma(rb, w3, facc[j][3]);
        }
    }

    float pwl[8];
#pragma unroll
    for (int k = 0; k < 8; k++) pwl[k] = spw[tc * 8 + k];
    float pbv = pb[0];

#pragma unroll
    for (int j = 0; j < 2; j++) {
        float s = 0.f;
#pragma unroll
        for (int p = 0; p < 4; p++) {
            float f0, f1;
            f2up(facc[j][p], f0, f1);
            s += tanhfast(f0) * pwl[2 * p] + tanhfast(f1) * pwl[2 * p + 1];
        }
        s += __shfl_xor_sync(0xffffffffu, s, 1);
        s += __shfl_xor_sync(0xffffffffu, s, 2);
        s += __shfl_xor_sync(0xffffffffu, s, 4);
        if (tc == 0) out[myrow0 + 4 * j] = s + pbv;
    }
}

// =====================================================================
extern "C" void kernel_launch(void* const* d_in, const int* in_sizes, int n_in,
                              void* d_out, int out_size)
{
    const int*   question = (const int*)d_in[0];
    const int*   response = (const int*)d_in[1];
    const float* mask     = (const float*)d_in[2];
    const float* k_emb    = (const float*)d_in[3];
    const float* v_emb    = (const float*)d_in[4];
    const float* Mk       = (const float*)d_in[5];
    const float* Mv0      = (const float*)d_in[6];
    const float* e_W      = (const float*)d_in[7];
    const float* e_b      = (const float*)d_in[8];
    const float* a_W      = (const float*)d_in[9];
    const float* a_b      = (const float*)d_in[10];
    const float* f_W      = (const float*)d_in[11];
    const float* f_b      = (const float*)d_in[12];
    const float* p_W      = (const float*)d_in[13];
    const float* p_b      = (const float*)d_in[14];
    float* out = (float*)d_out;

    k_build<<<WKFB + EAB, 128>>>(k_emb, Mk, f_W, f_b, v_emb, e_W, e_b, a_W, a_b);
    k_scan<<<128, 128>>>(Mv0, question, response, mask);
    k_head<<<511, 256>>>(question, f_W, p_W, p_b, out);

    (void)in_sizes; (void)n_in; (void)out_size;
}

// round 16
// speedup vs baseline: 1.5434x; 1.5434x over previous
#include <cuda_runtime.h>
#include <cuda_bf16.h>
#include <stdint.h>

typedef unsigned long long u64;

#define QNUM 10000
#define DNUM 64
#define MNUM 50
#define BNUM 64
#define TNUM 512
#define PART_STRIDE ((size_t)BNUM * (TNUM - 1) * DNUM)   // floats per partial stream

#define RB 48        // rows per build block
#define SVSTR 68     // padded staging stride (floats); 272B = 16B-aligned rows
#define WKFB 209     // ceil(10000/48)
#define EAB 417      // ceil(20000/48)

// ---------------- static scratch (no allocations allowed) ----------------
__device__ __align__(16) float g_kf [QNUM * DNUM];          // k-half of f-MLP + bias, per question id
__device__ __align__(16) float g_e  [2 * QNUM * DNUM];      // sigmoid erase per x id (raw)
__device__ __align__(16) float g_a  [2 * QNUM * DNUM];      // tanh add per x id (raw)
__device__ __align__(16) float g_wp [QNUM * 128];           // packed (w,w) pairs: pair j = w[m=j], j<50
__device__ __align__(16) float g_part[2 * PART_STRIDE];     // 2 partial read streams (split halves)

// ---------------- f32x2 helpers ----------------
__device__ __forceinline__ u64 f2pk(float a, float b) {
    u64 r; asm("mov.b64 %0,{%1,%2};" : "=l"(r) : "f"(a), "f"(b)); return r;
}
__device__ __forceinline__ u64 f2bc(float a) {
    u64 r; asm("mov.b64 %0,{%1,%1};" : "=l"(r) : "f"(a)); return r;
}
__device__ __forceinline__ void f2up(u64 v, float& a, float& b) {
    asm("mov.b64 {%0,%1},%2;" : "=f"(a), "=f"(b) : "l"(v));
}
__device__ __forceinline__ u64 f2fma(u64 a, u64 b, u64 c) {
    u64 d; asm("fma.rn.f32x2 %0,%1,%2,%3;" : "=l"(d) : "l"(a), "l"(b), "l"(c)); return d;
}
__device__ __forceinline__ u64 f2mul(u64 a, u64 b) {
    u64 d; asm("mul.rn.f32x2 %0,%1,%2;" : "=l"(d) : "l"(a), "l"(b)); return d;
}
__device__ __forceinline__ u64 f2add(u64 a, u64 b) {
    u64 d; asm("add.rn.f32x2 %0,%1,%2;" : "=l"(d) : "l"(a), "l"(b)); return d;
}

__device__ __forceinline__ float sigfast(float x) {
    return __fdividef(1.f, 1.f + __expf(-x));
}
__device__ __forceinline__ float tanhfast(float x) {
    x = fminf(fmaxf(x, -10.f), 10.f);
    float t = __expf(2.f * x);
    return (t - 1.f) * __fdividef(1.f, t + 1.f);
}

// ---------------- cp.async helpers ----------------
__device__ __forceinline__ void cpa16(uint32_t dst, const void* src) {
    asm volatile("cp.async.ca.shared.global [%0], [%1], 16;\n" :: "r"(dst), "l"(src));
}
__device__ __forceinline__ void cpcommit() { asm volatile("cp.async.commit_group;\n"); }
template <int N> __device__ __forceinline__ void cpwait() {
    asm volatile("cp.async.wait_group %0;\n" :: "n"(N));
}

// =====================================================================
// K1: precompute, fused dual-GEMM per block, 48 rows/CTA, 128 threads.
//   blocks [0,WKFB): logits->softmax (g_wp) + kf, per question id
//   blocks [WKFB,WKFB+EAB): e (sigmoid) + a (tanh) per v_emb row
// Thread = 3 rows x 4 strided d-pairs (j0 = 8p+tc) x 2 matrices.
// Both weight matrices resident in smem; single cp.async stage phase.
// =====================================================================
__global__ void __launch_bounds__(128) k_build(
    const float* __restrict__ k_emb, const float* __restrict__ Mk,
    const float* __restrict__ fW, const float* __restrict__ fb,
    const float* __restrict__ v_emb,
    const float* __restrict__ eW, const float* __restrict__ eb,
    const float* __restrict__ aW, const float* __restrict__ ab)
{
    __shared__ __align__(16) float sV[RB * SVSTR];   // 12.8KB staged input rows
    __shared__ __align__(16) u64 sW1[64 * 32];       // 16KB matrix 1 (pairs)
    __shared__ __align__(16) u64 sW2[64 * 32];       // 16KB matrix 2 (pairs)

    int tid = threadIdx.x;
    int warp = tid >> 5, lane = tid & 31;
    int tr = lane >> 3, tc = lane & 7;
    int lr0 = warp * 12 + tr;              // local rows lr0 + 4*j, j<3

    bool iswkf = blockIdx.x < WKFB;
    int rbase = iswkf ? blockIdx.x * RB : (blockIdx.x - WKFB) * RB;
    int nmax  = iswkf ? QNUM : 2 * QNUM;
    const float* src = iswkf ? k_emb : v_emb;

    uint32_t svd  = (uint32_t)__cvta_generic_to_shared(sV);
    uint32_t sw1d = (uint32_t)__cvta_generic_to_shared(sW1);
    uint32_t sw2d = (uint32_t)__cvta_generic_to_shared(sW2);

    // stage input rows (48 x 64 floats)
    for (int idx = tid; idx < RB * 16; idx += 128) {
        int r = idx >> 4, c = idx & 15;
        int row = min(rbase + r, nmax - 1);
        cpa16(svd + (r * SVSTR + c * 4) * 4, src + (size_t)row * 64 + c * 4);
    }
    // stage weight matrices
    if (iswkf) {
        for (int idx = tid; idx < 1024; idx += 128)
            cpa16(sw2d + idx * 16, fW + 4096 + idx * 4);     // fW rows 64..127
        // MkT pairs: sW1[i*32+j] = (Mk[2j][i], Mk[2j+1][i]), zero-padded m>=50
        for (int idx = tid; idx < 2048; idx += 128) {
            int j = idx & 31, i = idx >> 5;
            float a = (2 * j < MNUM) ? Mk[(2 * j) * 64 + i] : 0.f;
            float b = (2 * j + 1 < MNUM) ? Mk[(2 * j + 1) * 64 + i] : 0.f;
            sW1[i * 32 + j] = f2pk(a, b);
        }
    } else {
        for (int idx = tid; idx < 1024; idx += 128) {
            cpa16(sw1d + idx * 16, eW + idx * 4);
            cpa16(sw2d + idx * 16, aW + idx * 4);
        }
    }
    cpcommit();

    // init accumulators (strided pair j0 = 8p + tc); scalar bias loads
    u64 acc1[3][4], acc2[3][4];
    {
        const float* b2f = iswkf ? fb : ab;
#pragma unroll
        for (int p = 0; p < 4; p++) {
            int j0 = 8 * p + tc;
            u64 v1 = iswkf ? 0ull : f2pk(eb[2 * j0], eb[2 * j0 + 1]);
            u64 v2 = f2pk(b2f[2 * j0], b2f[2 * j0 + 1]);
#pragma unroll
            for (int j = 0; j < 3; j++) { acc1[j][p] = v1; acc2[j][p] = v2; }
        }
    }

    cpwait<0>();
    __syncthreads();

    // fused dual-GEMM mainloop
#pragma unroll 8
    for (int i = 0; i < 64; i++) {
        u64 w1[4], w2[4];
#pragma unroll
        for (int p = 0; p < 4; p++) {
            w1[p] = sW1[i * 32 + 8 * p + tc];
            w2[p] = sW2[i * 32 + 8 * p + tc];
        }
#pragma unroll
        for (int j = 0; j < 3; j++) {
            u64 rb = f2bc(sV[(lr0 + 4 * j) * SVSTR + i]);
            acc1[j][0] = f2fma(rb, w1[0], acc1[j][0]);
            acc2[j][0] = f2fma(rb, w2[0], acc2[j][0]);
            acc1[j][1] = f2fma(rb, w1[1], acc1[j][1]);
            acc2[j][1] = f2fma(rb, w2[1], acc2[j][1]);
            acc1[j][2] = f2fma(rb, w1[2], acc1[j][2]);
            acc2[j][2] = f2fma(rb, w2[2], acc2[j][2]);
            acc1[j][3] = f2fma(rb, w1[3], acc1[j][3]);
            acc2[j][3] = f2fma(rb, w2[3], acc2[j][3]);
        }
    }

    if (iswkf) {
        // softmax over m (thread owns m-pairs j0 = 8p+tc; pairs >=25 invalid)
#pragma unroll
        for (int j = 0; j < 3; j++) {
            int q = min(rbase + lr0 + 4 * j, QNUM - 1);
            float l[8];
#pragma unroll
            for (int p = 0; p < 4; p++) {
                f2up(acc1[j][p], l[2 * p], l[2 * p + 1]);
                if (8 * p + tc >= 25) { l[2 * p] = -3.0e38f; l[2 * p + 1] = -3.0e38f; }
            }
            float mx = l[0];
#pragma unroll
            for (int k = 1; k < 8; k++) mx = fmaxf(mx, l[k]);
            mx = fmaxf(mx, __shfl_xor_sync(0xffffffffu, mx, 1));
            mx = fmaxf(mx, __shfl_xor_sync(0xffffffffu, mx, 2));
            mx = fmaxf(mx, __shfl_xor_sync(0xffffffffu, mx, 4));
            float sm = 0.f;
#pragma unroll
            for (int k = 0; k < 8; k++) { l[k] = __expf(l[k] - mx); sm += l[k]; }
            sm += __shfl_xor_sync(0xffffffffu, sm, 1);
            sm += __shfl_xor_sync(0xffffffffu, sm, 2);
            sm += __shfl_xor_sync(0xffffffffu, sm, 4);
            float inv = __fdividef(1.f, sm);
            float* wp = g_wp + (size_t)q * 128;
            u64* kfd = (u64*)(g_kf + (size_t)q * 64);
#pragma unroll
            for (int p = 0; p < 4; p++) {
                int j0 = 8 * p + tc;
                float va = l[2 * p] * inv, vb = l[2 * p + 1] * inv;
                *(float4*)(wp + 4 * j0) = make_float4(va, va, vb, vb);
                kfd[j0] = acc2[j][p];
            }
        }
    } else {
        // e = sigmoid(acc1), a = tanh(acc2)
#pragma unroll
        for (int j = 0; j < 3; j++) {
            int x = min(rbase + lr0 + 4 * j, 2 * QNUM - 1);
            u64* ed = (u64*)(g_e + (size_t)x * 64);
            u64* ad = (u64*)(g_a + (size_t)x * 64);
#pragma unroll
            for (int p = 0; p < 4; p++) {
                int j0 = 8 * p + tc;
                float x0, x1;
                f2up(acc1[j][p], x0, x1);
                ed[j0] = f2pk(sigfast(x0), sigfast(x1));
                f2up(acc2[j][p], x0, x1);
                ad[j0] = f2pk(tanhfast(x0), tanhfast(x1));
            }
        }
    }
}

// =====================================================================
// K2: sequential scan with direct gather. 128 CTAs = (64 b) x (2 splits
// of 4 m-groups of 8), 4 warps/CTA. Uniform 8-slot groups. 16 steps per
// pipeline block, depth-3 cp.async.  (Exact round-10 version.)
// =====================================================================
__global__ void __launch_bounds__(128) k_scan(
    const float* __restrict__ Mv0,
    const int* __restrict__ question, const int* __restrict__ response,
    const float* __restrict__ mask)
{
    __shared__ __align__(16) char sme[3][4096];     // raw e rows   12KB
    __shared__ __align__(16) char sma[3][4096];     // raw a rows   12KB
    __shared__ __align__(16) char smw[3][4096];     // packed w     12KB
    __shared__ __align__(16) u64 stag[4][16][32];   // group partials 16KB
    __shared__ int   sxoff[512];                    // x-id * 256 (byte off)
    __shared__ int   sqoff[512];                    // q*512 + split*256
    __shared__ float smask[512];

    int b     = blockIdx.x & 63;
    int split = blockIdx.x >> 6;
    int tid = threadIdx.x;
    int g = tid >> 5, lane = tid & 31;     // local group 0..3
    int gg = split * 4 + g;                // global group 0..7
    int m0 = gg * 8;

    // ---- meta preload ----
    {
        int4 qa = ((const int4*)(question + b * 512))[tid];
        int4 ra = ((const int4*)(response + b * 512))[tid];
        float4 ma = ((const float4*)(mask + b * 512))[tid];
        int base = tid * 4;
        int so = split * 256;
        sxoff[base + 0] = (qa.x + QNUM * ra.x) * 256;  sqoff[base + 0] = qa.x * 512 + so;
        sxoff[base + 1] = (qa.y + QNUM * ra.y) * 256;  sqoff[base + 1] = qa.y * 512 + so;
        sxoff[base + 2] = (qa.z + QNUM * ra.z) * 256;  sqoff[base + 2] = qa.z * 512 + so;
        sxoff[base + 3] = (qa.w + QNUM * ra.w) * 256;  sqoff[base + 3] = qa.w * 512 + so;
        smask[base + 0] = ma.x; smask[base + 1] = ma.y;
        smask[base + 2] = ma.z; smask[base + 3] = ma.w;
    }

    u64 mv[8];
#pragma unroll
    for (int p = 0; p < 8; p++)
        mv[p] = (m0 + p < MNUM) ? *(const u64*)&Mv0[(m0 + p) * 64 + 2 * lane] : 0ull;

    __syncthreads();

    uint32_t sme_d = (uint32_t)__cvta_generic_to_shared(&sme[0][0]);
    uint32_t sma_d = (uint32_t)__cvta_generic_to_shared(&sma[0][0]);
    uint32_t smw_d = (uint32_t)__cvta_generic_to_shared(&smw[0][0]);
    const char* eB = (const char*)g_e;
    const char* aB = (const char*)g_a;
    const char* wB = (const char*)g_wp;

    auto issue = [&](int kb) {
        int buf = kb - (kb / 3) * 3;
        int t0 = kb * 16;
#pragma unroll
        for (int h = 0; h < 2; h++) {
            int c = tid + h * 128;            // 0..255 = 16 steps x 16 chunks
            int s = c >> 4, k16 = (c & 15) * 16;
            int xo = sxoff[t0 + s];
            int qo = sqoff[t0 + s];
            cpa16(sme_d + buf * 4096 + c * 16, eB + xo + k16);
            cpa16(sma_d + buf * 4096 + c * 16, aB + xo + k16);
            cpa16(smw_d + buf * 4096 + c * 16, wB + qo + k16);
        }
    };

    issue(0); cpcommit();
    issue(1); cpcommit();
    issue(2); cpcommit();

    float* pbase = g_part + split * PART_STRIDE + (size_t)b * 511 * 64 + 2 * lane;

    for (int kb = 0; kb < 32; kb++) {
        cpwait<2>();
        __syncthreads();
        int buf = kb - (kb / 3) * 3;
        const u64* eP = (const u64*)sme[buf];
        const u64* aP = (const u64*)sma[buf];
        const u64* wP = (const u64*)smw[buf];
#pragma unroll
        for (int s = 0; s < 16; s++) {
            float mt = smask[kb * 16 + s];
            u64 em2 = f2mul(eP[s * 32 + lane], f2bc(-mt));
            u64 am2 = f2mul(aP[s * 32 + lane], f2bc(mt));
            const u64* wr = wP + s * 32 + g * 8;
            u64 w0 = wr[0], w1 = wr[1], w2 = wr[2], w3 = wr[3],
                w4 = wr[4], w5 = wr[5], w6 = wr[6], w7 = wr[7];
            // read (state before this step's update)
            u64 p0 = f2mul(w0, mv[0]);
            u64 p1 = f2mul(w1, mv[1]);
            p0 = f2fma(w2, mv[2], p0);
            p1 = f2fma(w3, mv[3], p1);
            p0 = f2fma(w4, mv[4], p0);
            p1 = f2fma(w5, mv[5], p1);
            p0 = f2fma(w6, mv[6], p0);
            p1 = f2fma(w7, mv[7], p1);
            stag[g][s][lane] = f2add(p0, p1);
            // update: Mv += w * (mt*(a - e*Mv))
            u64 t0;
            t0 = f2fma(em2, mv[0], am2); mv[0] = f2fma(w0, t0, mv[0]);
            t0 = f2fma(em2, mv[1], am2); mv[1] = f2fma(w1, t0, mv[1]);
            t0 = f2fma(em2, mv[2], am2); mv[2] = f2fma(w2, t0, mv[2]);
            t0 = f2fma(em2, mv[3], am2); mv[3] = f2fma(w3, t0, mv[3]);
            t0 = f2fma(em2, mv[4], am2); mv[4] = f2fma(w4, t0, mv[4]);
            t0 = f2fma(em2, mv[5], am2); mv[5] = f2fma(w5, t0, mv[5]);
            t0 = f2fma(em2, mv[6], am2); mv[6] = f2fma(w6, t0, mv[6]);
            t0 = f2fma(em2, mv[7], am2); mv[7] = f2fma(w7, t0, mv[7]);
        }
        __syncthreads();
        // warp g reduces steps 4g..4g+3 across the CTA's 4 groups
#pragma unroll
        for (int ss = 0; ss < 4; ss++) {
            int so = g * 4 + ss;
            int t = kb * 16 + so;
            if (t > 0) {
                u64 a0 = f2add(stag[0][so][lane], stag[1][so][lane]);
                u64 a1 = f2add(stag[2][so][lane], stag[3][so][lane]);
                *(u64*)(pbase + (size_t)(t - 1) * 64) = f2add(a0, a1);
            }
        }
        if (kb + 3 < 32) issue(kb + 3);
        cpcommit();
    }
}

// =====================================================================
// K3: head as register-tiled GEMM. 64 rows/block, grid 511.
// (Exact round-10 version.)
// =====================================================================
#define RSTR 68   // padded read row stride in floats

__global__ void __launch_bounds__(256) k_head(
    const int* __restrict__ question, const float* __restrict__ fW,
    const float* __restrict__ pW, const float* __restrict__ pb,
    float* __restrict__ out)
{
    __shared__ __align__(16) float sW[64 * 64];
    __shared__ __align__(16) float sread[64 * RSTR];
    __shared__ float spw[64];

    int tid = threadIdx.x;
    int warp = tid >> 5, lane = tid & 31;
    int tr = lane >> 3, tc = lane & 7;
    int rbase = blockIdx.x * 64;

    {
        const float4* src = (const float4*)fW;
        float4* dst = (float4*)sW;
        for (int idx = tid; idx < 1024; idx += 256) dst[idx] = src[idx];
        if (tid < 64) spw[tid] = pW[tid];
    }

    {
        const float4* p0 = (const float4*)g_part;
        const float4* p1 = (const float4*)(g_part + PART_STRIDE);
#pragma unroll
        for (int k = 0; k < 4; k++) {
            int idx = k * 256 + tid;
            int r = idx >> 4, c = idx & 15;
            size_t grow = (size_t)(rbase + r) * 16 + c;
            float4 a = p0[grow];
            float4 b4 = p1[grow];
            float4 s;
            s.x = a.x + b4.x; s.y = a.y + b4.y; s.z = a.z + b4.z; s.w = a.w + b4.w;
            *(float4*)&sread[r * RSTR + c * 4] = s;
        }
    }

    int myrow0 = rbase + warp * 8 + tr;        // rows myrow0 + 4*j, j<2
    u64 facc[2][4];
#pragma unroll
    for (int j = 0; j < 2; j++) {
        int row = myrow0 + 4 * j;
        int b = row / 511;
        int tp = row - b * 511;
        int q = question[b * 512 + tp + 1];
        const float4* kfp = (const float4*)&g_kf[(size_t)q * 64 + tc * 8];
        float4 A = kfp[0], B = kfp[1];
        facc[j][0] = f2pk(A.x, A.y);
        facc[j][1] = f2pk(A.z, A.w);
        facc[j][2] = f2pk(B.x, B.y);
        facc[j][3] = f2pk(B.z, B.w);
    }
    __syncthreads();

    const u64* W = (const u64*)sW;
    const float* sr = &sread[(warp * 8 + tr) * RSTR];
#pragma unroll 8
    for (int i = 0; i < 64; i++) {
        u64 w0 = W[i * 32 + tc * 4 + 0];
        u64 w1 = W[i * 32 + tc * 4 + 1];
        u64 w2 = W[i * 32 + tc * 4 + 2];
        u64 w3 = W[i * 32 + tc * 4 + 3];
#pragma unroll
        for (int j = 0; j < 2; j++) {
            u64 rb = f2bc(sr[j * 4 * RSTR + i]);
            facc[j][0] = f2fma(rb, w0, facc[j][0]);
            facc[j][1] = f2fma(rb, w1, facc[j][1]);
            facc[j][2] = f2fma(rb, w2, facc[j][2]);
            facc[j][3] = f2fma(rb, w3, facc[j][3]);
        }
    }

    float pwl[8];
#pragma unroll
    for (int k = 0; k < 8; k++) pwl[k] = spw[tc * 8 + k];
    float pbv = pb[0];

#pragma unroll
    for (int j = 0; j < 2; j++) {
        float s = 0.f;
#pragma unroll
        for (int p = 0; p < 4; p++) {
            float f0, f1;
            f2up(facc[j][p], f0, f1);
            s += tanhfast(f0) * pwl[2 * p] + tanhfast(f1) * pwl[2 * p + 1];
        }
        s += __shfl_xor_sync(0xffffffffu, s, 1);
        s += __shfl_xor_sync(0xffffffffu, s, 2);
        s += __shfl_xor_sync(0xffffffffu, s, 4);
        if (tc == 0) out[myrow0 + 4 * j] = s + pbv;
    }
}

// =====================================================================
extern "C" void kernel_launch(void* const* d_in, const int* in_sizes, int n_in,
                              void* d_out, int out_size)
{
    const int*   question = (const int*)d_in[0];
    const int*   response = (const int*)d_in[1];
    const float* mask     = (const float*)d_in[2];
    const float* k_emb    = (const float*)d_in[3];
    const float* v_emb    = (const float*)d_in[4];
    const float* Mk       = (const float*)d_in[5];
    const float* Mv0      = (const float*)d_in[6];
    const float* e_W      = (const float*)d_in[7];
    const float* e_b      = (const float*)d_in[8];
    const float* a_W      = (const float*)d_in[9];
    const float* a_b      = (const float*)d_in[10];
    const float* f_W      = (const float*)d_in[11];
    const float* f_b      = (const float*)d_in[12];
    const float* p_W      = (const float*)d_in[13];
    const float* p_b      = (const float*)d_in[14];
    float* out = (float*)d_out;

    k_build<<<WKFB + EAB, 128>>>(k_emb, Mk, f_W, f_b, v_emb, e_W, e_b, a_W, a_b);
    k_scan<<<128, 128>>>(Mv0, question, response, mask);
    k_head<<<511, 256>>>(question, f_W, p_W, p_b, out);

    (void)in_sizes; (void)n_in; (void)out_size;
}